// round 3
// baseline (speedup 1.0000x reference)
#include <cuda_runtime.h>
#include <stdint.h>

#define IN_CH   128
#define OUT_CH  64
#define N_MAX   100000
#define E_MAX   1600000

// Scratch (device globals — no runtime allocation allowed)
__device__ float g_h[(size_t)N_MAX * OUT_CH];   // 25.6 MB: h = x @ W
__device__ float g_dinv[N_MAX];
__device__ int   g_deg[N_MAX];                  // includes self loop
__device__ int   g_off[N_MAX];                  // CSR offsets (edges only)
__device__ int   g_cur[N_MAX];                  // fill cursors
__device__ int2  g_csr[E_MAX];                  // .x = src, .y = bitcast(norm)

// ---------------------------------------------------------------------------
// Degree pipeline
// ---------------------------------------------------------------------------
__global__ void deg_init_kernel(int n) {
    int i = blockIdx.x * blockDim.x + threadIdx.x;
    if (i < n) g_deg[i] = 1;  // self loop
}

__global__ void deg_count_kernel(const int* __restrict__ dst, int e) {
    int i = blockIdx.x * blockDim.x + threadIdx.x;
    if (i < e) atomicAdd(&g_deg[dst[i]], 1);
}

__global__ void dinv_kernel(int n) {
    int i = blockIdx.x * blockDim.x + threadIdx.x;
    if (i < n) g_dinv[i] = rsqrtf((float)g_deg[i]);
}

// ---------------------------------------------------------------------------
// Single-block exclusive scan of per-node edge counts (deg-1) -> g_off, g_cur
// ---------------------------------------------------------------------------
__global__ __launch_bounds__(1024)
void scan_kernel(int n) {
    __shared__ int s[1024];
    const int tid = threadIdx.x;
    const int per = (n + 1023) / 1024;
    const int start = tid * per;
    const int end = min(start + per, n);

    int sum = 0;
    for (int i = start; i < end; i++) sum += g_deg[i] - 1;
    s[tid] = sum;
    __syncthreads();

    // Kogge-Stone inclusive scan
    for (int off = 1; off < 1024; off <<= 1) {
        int v = (tid >= off) ? s[tid - off] : 0;
        __syncthreads();
        s[tid] += v;
        __syncthreads();
    }
    int run = (tid == 0) ? 0 : s[tid - 1];
    for (int i = start; i < end; i++) {
        g_off[i] = run;
        g_cur[i] = run;
        run += g_deg[i] - 1;
    }
}

// ---------------------------------------------------------------------------
// CSR fill: bucket edges by destination, precompute norm per edge
// ---------------------------------------------------------------------------
__global__ __launch_bounds__(256)
void csr_fill_kernel(const int* __restrict__ src, const int* __restrict__ dst,
                     int e) {
    int i = blockIdx.x * blockDim.x + threadIdx.x;
    if (i >= e) return;
    int r = src[i];
    int c = dst[i];
    float norm = g_dinv[r] * g_dinv[c];
    int p = atomicAdd(&g_cur[c], 1);
    g_csr[p] = make_int2(r, __float_as_int(norm));
}

// ---------------------------------------------------------------------------
// GEMM: h = x @ W  (fp32, 128x64 tile per block, 8x4 per thread)
// ---------------------------------------------------------------------------
__global__ __launch_bounds__(256, 3)
void gemm_kernel(const float* __restrict__ x, const float* __restrict__ W,
                 int n) {
    __shared__ float xs[128][33];     // +1 pad vs bank conflicts
    __shared__ float ws[32][OUT_CH];  // k-chunk x all 64 cols

    const int tx  = threadIdx.x;      // 0..15 -> 4 cols each
    const int ty  = threadIdx.y;      // 0..15 -> 8 rows each
    const int tid = ty * 16 + tx;
    const int row0 = blockIdx.x * 128;

    float acc[8][4];
#pragma unroll
    for (int i = 0; i < 8; i++)
#pragma unroll
        for (int j = 0; j < 4; j++) acc[i][j] = 0.0f;

    for (int kc = 0; kc < IN_CH; kc += 32) {
        // Load x tile: 128 rows x 32 k = 1024 float4, 4 per thread
#pragma unroll
        for (int t = 0; t < 4; t++) {
            int li = tid + t * 256;     // 0..1023
            int r  = li >> 3;           // 0..127
            int k4 = li & 7;            // float4 index within 32
            float4 v = make_float4(0.f, 0.f, 0.f, 0.f);
            if (row0 + r < n)
                v = *(const float4*)(x + (size_t)(row0 + r) * IN_CH + kc + k4 * 4);
            xs[r][k4 * 4 + 0] = v.x;
            xs[r][k4 * 4 + 1] = v.y;
            xs[r][k4 * 4 + 2] = v.z;
            xs[r][k4 * 4 + 3] = v.w;
        }
        // Load W tile: 32 k x 64 cols = 512 float4, 2 per thread
#pragma unroll
        for (int t = 0; t < 2; t++) {
            int li = tid + t * 256;
            int k  = li >> 4;           // 0..31
            int c4 = li & 15;           // 0..15
            *(float4*)&ws[k][c4 * 4] =
                *(const float4*)(W + (size_t)(kc + k) * OUT_CH + c4 * 4);
        }
        __syncthreads();

#pragma unroll
        for (int kk = 0; kk < 32; kk++) {
            float4 b = *(float4*)&ws[kk][tx * 4];
#pragma unroll
            for (int i = 0; i < 8; i++) {
                float a = xs[ty * 8 + i][kk];
                acc[i][0] += a * b.x;
                acc[i][1] += a * b.y;
                acc[i][2] += a * b.z;
                acc[i][3] += a * b.w;
            }
        }
        __syncthreads();
    }

#pragma unroll
    for (int i = 0; i < 8; i++) {
        int r = row0 + ty * 8 + i;
        if (r < n) {
            *(float4*)(g_h + (size_t)r * OUT_CH + tx * 4) =
                make_float4(acc[i][0], acc[i][1], acc[i][2], acc[i][3]);
        }
    }
}

// ---------------------------------------------------------------------------
// Aggregate: 16 threads per node (one float4 column each). Registers
// accumulate in-edges from CSR + self loop; fused bias + ReLU on store.
// ---------------------------------------------------------------------------
__global__ __launch_bounds__(256)
void aggregate_kernel(const float* __restrict__ b, float* __restrict__ out,
                      int n) {
    int idx = blockIdx.x * blockDim.x + threadIdx.x;
    int v = idx >> 4;
    if (v >= n) return;
    int q = idx & 15;

    float dv = g_dinv[v];
    float d2 = dv * dv;

    // self-loop contribution
    float4 acc = *((const float4*)(g_h + (size_t)v * OUT_CH) + q);
    acc.x *= d2; acc.y *= d2; acc.z *= d2; acc.w *= d2;

    int j = g_off[v];
    const int e = j + (g_deg[v] - 1);

    // 4-way unroll for MLP on the random h gathers
    for (; j + 3 < e; j += 4) {
        int2 c0 = g_csr[j + 0];
        int2 c1 = g_csr[j + 1];
        int2 c2 = g_csr[j + 2];
        int2 c3 = g_csr[j + 3];
        float4 h0 = *((const float4*)(g_h + (size_t)c0.x * OUT_CH) + q);
        float4 h1 = *((const float4*)(g_h + (size_t)c1.x * OUT_CH) + q);
        float4 h2 = *((const float4*)(g_h + (size_t)c2.x * OUT_CH) + q);
        float4 h3 = *((const float4*)(g_h + (size_t)c3.x * OUT_CH) + q);
        float n0 = __int_as_float(c0.y), n1 = __int_as_float(c1.y);
        float n2 = __int_as_float(c2.y), n3 = __int_as_float(c3.y);
        acc.x += n0 * h0.x + n1 * h1.x + n2 * h2.x + n3 * h3.x;
        acc.y += n0 * h0.y + n1 * h1.y + n2 * h2.y + n3 * h3.y;
        acc.z += n0 * h0.z + n1 * h1.z + n2 * h2.z + n3 * h3.z;
        acc.w += n0 * h0.w + n1 * h1.w + n2 * h2.w + n3 * h3.w;
    }
    for (; j < e; j++) {
        int2 c = g_csr[j];
        float nm = __int_as_float(c.y);
        float4 hv = *((const float4*)(g_h + (size_t)c.x * OUT_CH) + q);
        acc.x += nm * hv.x; acc.y += nm * hv.y;
        acc.z += nm * hv.z; acc.w += nm * hv.w;
    }

    float4 bb = ((const float4*)b)[q];
    acc.x = fmaxf(acc.x + bb.x, 0.f);
    acc.y = fmaxf(acc.y + bb.y, 0.f);
    acc.z = fmaxf(acc.z + bb.z, 0.f);
    acc.w = fmaxf(acc.w + bb.w, 0.f);
    *((float4*)(out + (size_t)v * OUT_CH) + q) = acc;
}

// ---------------------------------------------------------------------------
extern "C" void kernel_launch(void* const* d_in, const int* in_sizes, int n_in,
                              void* d_out, int out_size) {
    const float* x  = (const float*)d_in[0];
    const int*   ei = (const int*)d_in[1];
    const float* W  = (const float*)d_in[2];
    const float* b  = (const float*)d_in[3];
    float*       out = (float*)d_out;

    const int n = in_sizes[0] / IN_CH;   // 100000
    const int e = in_sizes[1] / 2;       // 1600000
    const int* src = ei;                 // edge_index[0]
    const int* dst = ei + e;             // edge_index[1]

    deg_init_kernel<<<(n + 255) / 256, 256>>>(n);
    deg_count_kernel<<<(e + 255) / 256, 256>>>(dst, e);
    dinv_kernel<<<(n + 255) / 256, 256>>>(n);
    scan_kernel<<<1, 1024>>>(n);
    csr_fill_kernel<<<(e + 255) / 256, 256>>>(src, dst, e);

    dim3 tb(16, 16);
    gemm_kernel<<<(n + 127) / 128, tb>>>(x, W, n);

    long ag_threads = (long)n * 16;
    aggregate_kernel<<<(int)((ag_threads + 255) / 256), 256>>>(b, out, n);
}

// round 4
// speedup vs baseline: 2.0865x; 2.0865x over previous
#include <cuda_runtime.h>
#include <stdint.h>

#define IN_CH   128
#define OUT_CH  64
#define N_MAX   100000
#define E_MAX   1600000
#define SCAN_B  1024
#define NBLK    ((N_MAX + SCAN_B - 1) / SCAN_B)   // 98

// Scratch (device globals — no runtime allocation allowed)
__device__ float g_h[(size_t)N_MAX * OUT_CH];   // 25.6 MB: h = x @ W
__device__ float g_dinv[N_MAX];
__device__ int   g_deg[N_MAX];                  // includes self loop
__device__ int   g_off[N_MAX];                  // CSR offsets (edges only)
__device__ int   g_cur[N_MAX];                  // fill cursors
__device__ int   g_bsum[NBLK];                  // per-block sums for scan
__device__ int2  g_csr[E_MAX];                  // .x = src, .y = bitcast(norm)

// ---------------------------------------------------------------------------
// Degree pipeline
// ---------------------------------------------------------------------------
__global__ void deg_init_kernel(int n) {
    int i = blockIdx.x * blockDim.x + threadIdx.x;
    if (i < n) g_deg[i] = 1;  // self loop
}

__global__ void deg_count_kernel(const int* __restrict__ dst, int e) {
    int i = blockIdx.x * blockDim.x + threadIdx.x;
    if (i < e) atomicAdd(&g_deg[dst[i]], 1);
}

__global__ void dinv_kernel(int n) {
    int i = blockIdx.x * blockDim.x + threadIdx.x;
    if (i < n) g_dinv[i] = rsqrtf((float)g_deg[i]);
}

// ---------------------------------------------------------------------------
// Hierarchical scan of (deg-1): block-local scan + block sums
// ---------------------------------------------------------------------------
__global__ __launch_bounds__(SCAN_B)
void scan_block_kernel(int n) {
    __shared__ int s[SCAN_B];
    int tid = threadIdx.x;
    int i = blockIdx.x * SCAN_B + tid;
    int c = (i < n) ? (g_deg[i] - 1) : 0;
    s[tid] = c;
    __syncthreads();
#pragma unroll
    for (int off = 1; off < SCAN_B; off <<= 1) {
        int v = (tid >= off) ? s[tid - off] : 0;
        __syncthreads();
        s[tid] += v;
        __syncthreads();
    }
    if (i < n) g_off[i] = s[tid] - c;   // exclusive within block
    if (tid == SCAN_B - 1) g_bsum[blockIdx.x] = s[tid];
}

__global__ __launch_bounds__(128)
void scan_bsums_kernel() {
    __shared__ int s[128];
    int tid = threadIdx.x;
    int v = (tid < NBLK) ? g_bsum[tid] : 0;
    s[tid] = v;
    __syncthreads();
#pragma unroll
    for (int off = 1; off < 128; off <<= 1) {
        int t = (tid >= off) ? s[tid - off] : 0;
        __syncthreads();
        s[tid] += t;
        __syncthreads();
    }
    if (tid < NBLK) g_bsum[tid] = s[tid] - v;  // exclusive
}

__global__ __launch_bounds__(SCAN_B)
void scan_apply_kernel(int n) {
    int i = blockIdx.x * SCAN_B + threadIdx.x;
    if (i < n) {
        int o = g_off[i] + g_bsum[blockIdx.x];
        g_off[i] = o;
        g_cur[i] = o;
    }
}

// ---------------------------------------------------------------------------
// CSR fill: bucket edges by destination, precompute norm per edge
// ---------------------------------------------------------------------------
__global__ __launch_bounds__(256)
void csr_fill_kernel(const int* __restrict__ src, const int* __restrict__ dst,
                     int e) {
    int i = blockIdx.x * blockDim.x + threadIdx.x;
    if (i >= e) return;
    int r = src[i];
    int c = dst[i];
    float norm = g_dinv[r] * g_dinv[c];
    int p = atomicAdd(&g_cur[c], 1);
    g_csr[p] = make_int2(r, __float_as_int(norm));
}

// ---------------------------------------------------------------------------
// GEMM: h = x @ W  (fp32, 128x64 tile per block, 8x4 per thread)
// ---------------------------------------------------------------------------
__global__ __launch_bounds__(256, 3)
void gemm_kernel(const float* __restrict__ x, const float* __restrict__ W,
                 int n) {
    __shared__ float xs[128][33];     // +1 pad vs bank conflicts
    __shared__ float ws[32][OUT_CH];  // k-chunk x all 64 cols

    const int tx  = threadIdx.x;      // 0..15 -> 4 cols each
    const int ty  = threadIdx.y;      // 0..15 -> 8 rows each
    const int tid = ty * 16 + tx;
    const int row0 = blockIdx.x * 128;

    float acc[8][4];
#pragma unroll
    for (int i = 0; i < 8; i++)
#pragma unroll
        for (int j = 0; j < 4; j++) acc[i][j] = 0.0f;

    for (int kc = 0; kc < IN_CH; kc += 32) {
#pragma unroll
        for (int t = 0; t < 4; t++) {
            int li = tid + t * 256;     // 0..1023
            int r  = li >> 3;           // 0..127
            int k4 = li & 7;
            float4 v = make_float4(0.f, 0.f, 0.f, 0.f);
            if (row0 + r < n)
                v = *(const float4*)(x + (size_t)(row0 + r) * IN_CH + kc + k4 * 4);
            xs[r][k4 * 4 + 0] = v.x;
            xs[r][k4 * 4 + 1] = v.y;
            xs[r][k4 * 4 + 2] = v.z;
            xs[r][k4 * 4 + 3] = v.w;
        }
#pragma unroll
        for (int t = 0; t < 2; t++) {
            int li = tid + t * 256;
            int k  = li >> 4;
            int c4 = li & 15;
            *(float4*)&ws[k][c4 * 4] =
                *(const float4*)(W + (size_t)(kc + k) * OUT_CH + c4 * 4);
        }
        __syncthreads();

#pragma unroll
        for (int kk = 0; kk < 32; kk++) {
            float4 b = *(float4*)&ws[kk][tx * 4];
#pragma unroll
            for (int i = 0; i < 8; i++) {
                float a = xs[ty * 8 + i][kk];
                acc[i][0] += a * b.x;
                acc[i][1] += a * b.y;
                acc[i][2] += a * b.z;
                acc[i][3] += a * b.w;
            }
        }
        __syncthreads();
    }

#pragma unroll
    for (int i = 0; i < 8; i++) {
        int r = row0 + ty * 8 + i;
        if (r < n) {
            *(float4*)(g_h + (size_t)r * OUT_CH + tx * 4) =
                make_float4(acc[i][0], acc[i][1], acc[i][2], acc[i][3]);
        }
    }
}

// ---------------------------------------------------------------------------
// Aggregate: 16 threads per node (one float4 column each). Registers
// accumulate in-edges from CSR + self loop; fused bias + ReLU on store.
// ---------------------------------------------------------------------------
__global__ __launch_bounds__(256)
void aggregate_kernel(const float* __restrict__ b, float* __restrict__ out,
                      int n) {
    int idx = blockIdx.x * blockDim.x + threadIdx.x;
    int v = idx >> 4;
    if (v >= n) return;
    int q = idx & 15;

    float dv = g_dinv[v];
    float d2 = dv * dv;

    // self-loop contribution
    float4 acc = *((const float4*)(g_h + (size_t)v * OUT_CH) + q);
    acc.x *= d2; acc.y *= d2; acc.z *= d2; acc.w *= d2;

    int j = g_off[v];
    const int e = j + (g_deg[v] - 1);

    // 4-way unroll for MLP on the random h gathers
    for (; j + 3 < e; j += 4) {
        int2 c0 = g_csr[j + 0];
        int2 c1 = g_csr[j + 1];
        int2 c2 = g_csr[j + 2];
        int2 c3 = g_csr[j + 3];
        float4 h0 = *((const float4*)(g_h + (size_t)c0.x * OUT_CH) + q);
        float4 h1 = *((const float4*)(g_h + (size_t)c1.x * OUT_CH) + q);
        float4 h2 = *((const float4*)(g_h + (size_t)c2.x * OUT_CH) + q);
        float4 h3 = *((const float4*)(g_h + (size_t)c3.x * OUT_CH) + q);
        float n0 = __int_as_float(c0.y), n1 = __int_as_float(c1.y);
        float n2 = __int_as_float(c2.y), n3 = __int_as_float(c3.y);
        acc.x += n0 * h0.x + n1 * h1.x + n2 * h2.x + n3 * h3.x;
        acc.y += n0 * h0.y + n1 * h1.y + n2 * h2.y + n3 * h3.y;
        acc.z += n0 * h0.z + n1 * h1.z + n2 * h2.z + n3 * h3.z;
        acc.w += n0 * h0.w + n1 * h1.w + n2 * h2.w + n3 * h3.w;
    }
    for (; j < e; j++) {
        int2 c = g_csr[j];
        float nm = __int_as_float(c.y);
        float4 hv = *((const float4*)(g_h + (size_t)c.x * OUT_CH) + q);
        acc.x += nm * hv.x; acc.y += nm * hv.y;
        acc.z += nm * hv.z; acc.w += nm * hv.w;
    }

    float4 bb = ((const float4*)b)[q];
    acc.x = fmaxf(acc.x + bb.x, 0.f);
    acc.y = fmaxf(acc.y + bb.y, 0.f);
    acc.z = fmaxf(acc.z + bb.z, 0.f);
    acc.w = fmaxf(acc.w + bb.w, 0.f);
    *((float4*)(out + (size_t)v * OUT_CH) + q) = acc;
}

// ---------------------------------------------------------------------------
extern "C" void kernel_launch(void* const* d_in, const int* in_sizes, int n_in,
                              void* d_out, int out_size) {
    const float* x  = (const float*)d_in[0];
    const int*   ei = (const int*)d_in[1];
    const float* W  = (const float*)d_in[2];
    const float* b  = (const float*)d_in[3];
    float*       out = (float*)d_out;

    const int n = in_sizes[0] / IN_CH;   // 100000
    const int e = in_sizes[1] / 2;       // 1600000
    const int* src = ei;                 // edge_index[0]
    const int* dst = ei + e;             // edge_index[1]

    deg_init_kernel<<<(n + 255) / 256, 256>>>(n);
    deg_count_kernel<<<(e + 255) / 256, 256>>>(dst, e);
    dinv_kernel<<<(n + 255) / 256, 256>>>(n);

    int nblk = (n + SCAN_B - 1) / SCAN_B;
    scan_block_kernel<<<nblk, SCAN_B>>>(n);
    scan_bsums_kernel<<<1, 128>>>();
    scan_apply_kernel<<<nblk, SCAN_B>>>(n);

    csr_fill_kernel<<<(e + 255) / 256, 256>>>(src, dst, e);

    dim3 tb(16, 16);
    gemm_kernel<<<(n + 127) / 128, tb>>>(x, W, n);

    long ag_threads = (long)n * 16;
    aggregate_kernel<<<(int)((ag_threads + 255) / 256), 256>>>(b, out, n);
}